// round 2
// baseline (speedup 1.0000x reference)
#include <cuda_runtime.h>

#define NAGENT 32768
#define NBRS   16
#define H      128
#define FN     32
#define FH     8
#define FE     (FN + FH)   // 40 per-edge varying input channels
#define NPOW   4
#define AG     4           // agents per CTA
#define QCOLS  (NBRS * NPOW + 1)  // 65

__global__ __launch_bounds__(128, 6)
void fused_graphq(
    const float* __restrict__ feat_nbr,
    const float* __restrict__ feat_agent,
    const float* __restrict__ edge_feat,
    const float* __restrict__ h_in,
    const float* __restrict__ W_msg, const float* __restrict__ b_msg,
    const float* __restrict__ W_upd, const float* __restrict__ b_upd,
    const float* __restrict__ W_x,   const float* __restrict__ W_h,
    const float* __restrict__ b_ih,  const float* __restrict__ b_hh,
    const float* __restrict__ W_e1,  const float* __restrict__ b_e1,
    const float* __restrict__ W_e2,  const float* __restrict__ b_e2,
    const float* __restrict__ W_a,   const float* __restrict__ b_a,
    const int*   __restrict__ src_idx,
    float* __restrict__ q_out,   // [N, 65]
    float* __restrict__ h_out)   // [N, 128]
{
    const int k  = threadIdx.x;          // output channel 0..127
    const int a0 = blockIdx.x * AG;      // first agent of this CTA
    const int e0 = a0 * NBRS;            // first edge

    // all per-agent vectors transposed: [channel][agent]
    __shared__ __align__(16) float in_s[FE][AG * NBRS];  // edge inputs [40][64]
    __shared__ __align__(16) float x_s[H + FN][AG];      // agg(0..127)+feat_agent(128..159)
    __shared__ __align__(16) float h_s[H][AG];
    __shared__ __align__(16) float xo_s[H][AG];          // x (post-update MLP)
    __shared__ __align__(16) float hn_s[H][AG];          // h_new
    __shared__ __align__(16) float ze_s[H][NBRS];        // one agent's ze, reused
    __shared__ float red_s[4][AG];

    // ---------------- load phase ----------------
    {
        int j = k >> 1;          // edge 0..63 within CTA
        int half = k & 1;
        int src = src_idx[e0 + j];
        const float4* fn = reinterpret_cast<const float4*>(feat_nbr + (size_t)src * FN);
        #pragma unroll
        for (int i = 0; i < 4; i++) {
            float4 v = __ldg(&fn[half * 4 + i]);
            int c = half * 16 + i * 4;
            in_s[c + 0][j] = v.x; in_s[c + 1][j] = v.y;
            in_s[c + 2][j] = v.z; in_s[c + 3][j] = v.w;
        }
        const float4* ef = reinterpret_cast<const float4*>(edge_feat + (size_t)(e0 + j) * FH);
        float4 u = __ldg(&ef[half]);
        int c = FN + half * 4;
        in_s[c + 0][j] = u.x; in_s[c + 1][j] = u.y;
        in_s[c + 2][j] = u.z; in_s[c + 3][j] = u.w;
    }
    {   // feat_agent -> x_s rows 128..159
        int a = k >> 5, c = k & 31;
        x_s[H + c][a] = feat_agent[(size_t)(a0 + a) * FN + c];
    }
    #pragma unroll
    for (int a = 0; a < AG; a++)
        h_s[k][a] = h_in[(size_t)(a0 + a) * H + k];
    __syncthreads();

    // ---------------- stage A: msg MLP + aggregate ----------------
    {
        const float bm = __ldg(&b_msg[k]);
        float aggv[AG];
        #pragma unroll
        for (int a = 0; a < AG; a++) {
            float s = 0.f;
            #pragma unroll
            for (int bj = 0; bj < 4; bj++) {
                int j0 = a * NBRS + bj * 4;
                float ac[4] = {bm, bm, bm, bm};
                #pragma unroll 8
                for (int c = 0; c < FE; c++) {
                    float w = __ldg(&W_msg[c * H + k]);
                    float v[4];
                    *reinterpret_cast<float4*>(v) =
                        *reinterpret_cast<const float4*>(&in_s[c][j0]);
                    #pragma unroll
                    for (int q = 0; q < 4; q++) ac[q] = fmaf(w, v[q], ac[q]);
                }
                #pragma unroll
                for (int q = 0; q < 4; q++) s += fmaxf(ac[q], 0.f);
            }
            aggv[a] = s;
        }
        *reinterpret_cast<float4*>(&x_s[k][0]) =
            make_float4(aggv[0], aggv[1], aggv[2], aggv[3]);
    }
    __syncthreads();

    // ---------------- stage B: update MLP ----------------
    {
        const float bu = __ldg(&b_upd[k]);
        float ac[AG] = {bu, bu, bu, bu};
        #pragma unroll 8
        for (int c = 0; c < H + FN; c++) {
            float w = __ldg(&W_upd[c * H + k]);
            float v[4];
            *reinterpret_cast<float4*>(v) = *reinterpret_cast<const float4*>(&x_s[c][0]);
            #pragma unroll
            for (int a = 0; a < AG; a++) ac[a] = fmaf(w, v[a], ac[a]);
        }
        *reinterpret_cast<float4*>(&xo_s[k][0]) =
            make_float4(fmaxf(ac[0], 0.f), fmaxf(ac[1], 0.f),
                        fmaxf(ac[2], 0.f), fmaxf(ac[3], 0.f));
    }
    __syncthreads();

    // ---------------- stage C: GRU ----------------
    float hnew[AG];
    {
        float rr[AG], zz[AG], nn[AG], hh[AG];
        float bir = __ldg(&b_ih[k]),         bhr = __ldg(&b_hh[k]);
        float biz = __ldg(&b_ih[H + k]),     bhz = __ldg(&b_hh[H + k]);
        float bin = __ldg(&b_ih[2 * H + k]), bhn = __ldg(&b_hh[2 * H + k]);
        #pragma unroll
        for (int a = 0; a < AG; a++) {
            rr[a] = bir + bhr; zz[a] = biz + bhz; nn[a] = bin; hh[a] = bhn;
        }
        #pragma unroll 4
        for (int c = 0; c < H; c++) {
            float xv[4], hv[4];
            *reinterpret_cast<float4*>(xv) = *reinterpret_cast<const float4*>(&xo_s[c][0]);
            *reinterpret_cast<float4*>(hv) = *reinterpret_cast<const float4*>(&h_s[c][0]);
            const float* wx = W_x + (size_t)c * 3 * H;
            const float* wh = W_h + (size_t)c * 3 * H;
            float wr = __ldg(wx + k), wz = __ldg(wx + H + k), wn = __ldg(wx + 2 * H + k);
            float ur = __ldg(wh + k), uz = __ldg(wh + H + k), un = __ldg(wh + 2 * H + k);
            #pragma unroll
            for (int a = 0; a < AG; a++) {
                rr[a] = fmaf(wr, xv[a], rr[a]); rr[a] = fmaf(ur, hv[a], rr[a]);
                zz[a] = fmaf(wz, xv[a], zz[a]); zz[a] = fmaf(uz, hv[a], zz[a]);
                nn[a] = fmaf(wn, xv[a], nn[a]); hh[a] = fmaf(un, hv[a], hh[a]);
            }
        }
        #pragma unroll
        for (int a = 0; a < AG; a++) {
            float r = 1.f / (1.f + __expf(-rr[a]));
            float z = 1.f / (1.f + __expf(-zz[a]));
            float n = tanhf(nn[a] + r * hh[a]);
            float hv = h_s[k][a];
            hnew[a] = (1.f - z) * n + z * hv;
            h_out[(size_t)(a0 + a) * H + k] = hnew[a];
        }
        *reinterpret_cast<float4*>(&hn_s[k][0]) =
            make_float4(hnew[0], hnew[1], hnew[2], hnew[3]);
    }
    __syncthreads();

    // ---------------- stage D: e1 h_new part (shared across 16 edges) ----------------
    float tA[AG];
    {
        const float be = __ldg(&b_e1[k]);
        #pragma unroll
        for (int a = 0; a < AG; a++) tA[a] = be;
        #pragma unroll 4
        for (int c = 0; c < H; c++) {
            float w = __ldg(&W_e1[(FN + c) * H + k]);
            float v[4];
            *reinterpret_cast<float4*>(v) = *reinterpret_cast<const float4*>(&hn_s[c][0]);
            #pragma unroll
            for (int a = 0; a < AG; a++) tA[a] = fmaf(w, v[a], tA[a]);
        }
    }

    // ---------------- stage E/F: e1 edge part, e2, agg2 (per agent) ----------------
    float agg2[AG];
    for (int a = 0; a < AG; a++) {
        float s2 = 0.f;
        #pragma unroll
        for (int bj = 0; bj < 4; bj++) {
            int j0 = a * NBRS + bj * 4;
            float ac[4] = {tA[a], tA[a], tA[a], tA[a]};
            #pragma unroll 8
            for (int c = 0; c < FE; c++) {
                int row = (c < FN) ? c : (c + H);   // edge_feat rows live at 160..167
                float w = __ldg(&W_e1[row * H + k]);
                float v[4];
                *reinterpret_cast<float4*>(v) =
                    *reinterpret_cast<const float4*>(&in_s[c][j0]);
                #pragma unroll
                for (int q = 0; q < 4; q++) ac[q] = fmaf(w, v[q], ac[q]);
            }
            float z0 = fmaxf(ac[0], 0.f), z1 = fmaxf(ac[1], 0.f);
            float z2 = fmaxf(ac[2], 0.f), z3 = fmaxf(ac[3], 0.f);
            s2 += z0 + z1 + z2 + z3;
            *reinterpret_cast<float4*>(&ze_s[k][bj * 4]) = make_float4(z0, z1, z2, z3);
        }
        agg2[a] = s2;
        __syncthreads();
        if (k < NBRS * NPOW) {   // 64 threads: edge q-values
            int j = k & 15, p = k >> 4;
            float o = __ldg(&b_e2[p]);
            #pragma unroll 8
            for (int kk = 0; kk < H; kk++)
                o = fmaf(ze_s[kk][j], __ldg(&W_e2[kk * NPOW + p]), o);
            q_out[(size_t)(a0 + a) * QCOLS + j * NPOW + p] = o;
        }
        __syncthreads();
    }

    // ---------------- head: agent_out ----------------
    {
        float wa = __ldg(&W_a[k]);
        float wh = __ldg(&W_a[H + k]);
        float part[AG];
        #pragma unroll
        for (int a = 0; a < AG; a++)
            part[a] = agg2[a] * wa + hnew[a] * wh;
        #pragma unroll
        for (int off = 16; off > 0; off >>= 1)
            #pragma unroll
            for (int a = 0; a < AG; a++)
                part[a] += __shfl_down_sync(0xffffffffu, part[a], off);
        int warp = k >> 5, lane = k & 31;
        if (lane == 0)
            #pragma unroll
            for (int a = 0; a < AG; a++) red_s[warp][a] = part[a];
        __syncthreads();
        if (k < AG) {
            float o = __ldg(&b_a[0]) +
                      red_s[0][k] + red_s[1][k] + red_s[2][k] + red_s[3][k];
            q_out[(size_t)(a0 + k) * QCOLS + NBRS * NPOW] = o;
        }
    }
}

extern "C" void kernel_launch(void* const* d_in, const int* in_sizes, int n_in,
                              void* d_out, int out_size) {
    (void)in_sizes; (void)n_in; (void)out_size;
    float* out = (float*)d_out;
    fused_graphq<<<NAGENT / AG, 128>>>(
        (const float*)d_in[0],  // feat_nbr
        (const float*)d_in[1],  // feat_agent
        (const float*)d_in[2],  // edge_feat
        (const float*)d_in[3],  // h
        (const float*)d_in[4],  (const float*)d_in[5],   // W_msg, b_msg
        (const float*)d_in[6],  (const float*)d_in[7],   // W_upd, b_upd
        (const float*)d_in[8],  (const float*)d_in[9],   // W_x, W_h
        (const float*)d_in[10], (const float*)d_in[11],  // b_ih, b_hh
        (const float*)d_in[12], (const float*)d_in[13],  // W_e1, b_e1
        (const float*)d_in[14], (const float*)d_in[15],  // W_e2, b_e2
        (const float*)d_in[16], (const float*)d_in[17],  // W_a, b_a
        (const int*)d_in[18],                            // src_idx (dst_idx unused: repeat(arange))
        out,                                             // q_vals [N,65]
        out + (size_t)NAGENT * QCOLS);                   // h_new  [N,128]
}